// round 1
// baseline (speedup 1.0000x reference)
#include <cuda_runtime.h>
#include <cuda_bf16.h>
#include <math.h>

// Problem constants
constexpr int S = 4096, HID = 2048, HQ = 16, HKV = 8, D = 128, WINDOW = 1024;

// Scratch (device globals -- no allocation allowed)
__device__ float g_q[(size_t)S * HQ * D];     // [S, HQ, D]
__device__ float g_k[(size_t)S * HKV * D];    // [S, HKV, D]
__device__ float g_v[(size_t)S * HKV * D];    // [S, HKV, D]
__device__ float g_att[(size_t)S * HQ * D];   // [S, HQ, D]

// ---------------------------------------------------------------------------
// SGEMM: C[M,N] = A[M,K] @ B[N,K]^T   (A,B,C row-major, all dims % 128 == 0)
// 128x128 block tile, BK=8, 256 threads, 8x8 per-thread microtile.
// ---------------------------------------------------------------------------
__global__ __launch_bounds__(256, 2)
void sgemm_nt(const float* __restrict__ A, const float* __restrict__ B,
              float* __restrict__ C, int M, int N, int Kd) {
    __shared__ float As[8][128];
    __shared__ float Bs[8][128];
    const int tid = threadIdx.x;
    const int bm = blockIdx.y * 128;
    const int bn = blockIdx.x * 128;
    const int tx = tid & 15;
    const int ty = tid >> 4;

    float acc[8][8];
#pragma unroll
    for (int i = 0; i < 8; i++)
#pragma unroll
        for (int j = 0; j < 8; j++) acc[i][j] = 0.f;

    const int lrow = tid >> 1;
    const int lcol = (tid & 1) * 4;
    const float* Ap = A + (size_t)(bm + lrow) * Kd + lcol;
    const float* Bp = B + (size_t)(bn + lrow) * Kd + lcol;

    for (int k0 = 0; k0 < Kd; k0 += 8) {
        float4 av = *(const float4*)(Ap + k0);
        float4 bv = *(const float4*)(Bp + k0);
        __syncthreads();
        As[lcol + 0][lrow] = av.x; As[lcol + 1][lrow] = av.y;
        As[lcol + 2][lrow] = av.z; As[lcol + 3][lrow] = av.w;
        Bs[lcol + 0][lrow] = bv.x; Bs[lcol + 1][lrow] = bv.y;
        Bs[lcol + 2][lrow] = bv.z; Bs[lcol + 3][lrow] = bv.w;
        __syncthreads();
#pragma unroll
        for (int kk = 0; kk < 8; kk++) {
            float a[8], b[8];
            *(float4*)&a[0] = *(const float4*)&As[kk][ty * 8];
            *(float4*)&a[4] = *(const float4*)&As[kk][ty * 8 + 4];
            *(float4*)&b[0] = *(const float4*)&Bs[kk][tx * 8];
            *(float4*)&b[4] = *(const float4*)&Bs[kk][tx * 8 + 4];
#pragma unroll
            for (int i = 0; i < 8; i++)
#pragma unroll
                for (int j = 0; j < 8; j++)
                    acc[i][j] = fmaf(a[i], b[j], acc[i][j]);
        }
    }

#pragma unroll
    for (int i = 0; i < 8; i++) {
        float* cp = C + (size_t)(bm + ty * 8 + i) * N + bn + tx * 8;
        *(float4*)cp       = make_float4(acc[i][0], acc[i][1], acc[i][2], acc[i][3]);
        *(float4*)(cp + 4) = make_float4(acc[i][4], acc[i][5], acc[i][6], acc[i][7]);
    }
}

// ---------------------------------------------------------------------------
// Fused RMSNorm + RoPE, in place on X = [S, H, D]. One block per (s,h) row.
// ---------------------------------------------------------------------------
__global__ __launch_bounds__(128)
void rmsnorm_rope(float* __restrict__ X, const float* __restrict__ w,
                  const float* __restrict__ cosp, const float* __restrict__ sinp,
                  int H) {
    const int s = blockIdx.x, h = blockIdx.y, d = threadIdx.x;
    float* row = X + ((size_t)s * H + h) * D;
    float x = row[d];
    float sq = x * x;
#pragma unroll
    for (int o = 16; o > 0; o >>= 1) sq += __shfl_xor_sync(0xffffffffu, sq, o);
    __shared__ float red[4];
    __shared__ float xs[D];
    if ((d & 31) == 0) red[d >> 5] = sq;
    __syncthreads();
    float var = (red[0] + red[1] + red[2] + red[3]) * (1.0f / D);
    float xn = x * rsqrtf(var + 1e-6f) * w[d];
    xs[d] = xn;
    __syncthreads();
    float other = (d < 64) ? -xs[d + 64] : xs[d - 64];
    row[d] = fmaf(xn, cosp[s * D + d], other * sinp[s * D + d]);
}

// ---------------------------------------------------------------------------
// Sliding-window flash attention (fp32). Block = 64 queries x 4 lanes/query.
// Each lane owns 32 interleaved dims (chunks u*16 + ld*4) -> conflict-free LDS.
// ---------------------------------------------------------------------------
__global__ __launch_bounds__(256, 2)
void attn_kernel() {
    const int h   = blockIdx.y;       // query head 0..15
    const int kh  = h >> 1;           // kv head (G=2)
    const int qt  = blockIdx.x;       // 64-query tile
    const int tid = threadIdx.x;
    const int qi  = qt * 64 + (tid >> 2);
    const int ld  = tid & 3;

    __shared__ float Ks[32][128];
    __shared__ float Vs[32][128];

    float qr[32];
    const float* qp = g_q + ((size_t)qi * HQ + h) * D;
#pragma unroll
    for (int u = 0; u < 8; u++)
        *(float4*)&qr[u * 4] = *(const float4*)(qp + u * 16 + ld * 4);

    float m = -1e30f, l = 0.f;
    float acc[32];
#pragma unroll
    for (int d = 0; d < 32; d++) acc[d] = 0.f;

    int jlo = qt * 64 - (WINDOW - 1);
    if (jlo < 0) jlo = 0;
    int j0 = jlo & ~31;
    const int jend = qt * 64 + 64;

    for (; j0 < jend; j0 += 32) {
        __syncthreads();
#pragma unroll
        for (int u = 0; u < 4; u++) {
            int idx = tid + u * 256;           // 0..1023 float4 slots
            int r = idx >> 5;                  // 32 float4 per row
            int c = (idx & 31) * 4;
            size_t goff = ((size_t)(j0 + r) * HKV + kh) * D + c;
            *(float4*)&Ks[r][c] = *(const float4*)(g_k + goff);
            *(float4*)&Vs[r][c] = *(const float4*)(g_v + goff);
        }
        __syncthreads();

        for (int j = 0; j < 32; j++) {
            const int jj = j0 + j;
            float sv = 0.f;
#pragma unroll
            for (int u = 0; u < 8; u++) {
                float4 kv = *(const float4*)&Ks[j][u * 16 + ld * 4];
                sv = fmaf(qr[u * 4 + 0], kv.x, sv);
                sv = fmaf(qr[u * 4 + 1], kv.y, sv);
                sv = fmaf(qr[u * 4 + 2], kv.z, sv);
                sv = fmaf(qr[u * 4 + 3], kv.w, sv);
            }
            sv += __shfl_xor_sync(0xffffffffu, sv, 1);
            sv += __shfl_xor_sync(0xffffffffu, sv, 2);
            if (jj <= qi && jj > qi - WINDOW) {
                sv *= 0.088388347648318447f;   // D^{-1/2}
                if (sv > m) {
                    const float c = __expf(m - sv);
                    l *= c;
#pragma unroll
                    for (int d = 0; d < 32; d++) acc[d] *= c;
                    m = sv;
                }
                const float p = __expf(sv - m);
                l += p;
#pragma unroll
                for (int u = 0; u < 8; u++) {
                    float4 vv = *(const float4*)&Vs[j][u * 16 + ld * 4];
                    acc[u * 4 + 0] = fmaf(p, vv.x, acc[u * 4 + 0]);
                    acc[u * 4 + 1] = fmaf(p, vv.y, acc[u * 4 + 1]);
                    acc[u * 4 + 2] = fmaf(p, vv.z, acc[u * 4 + 2]);
                    acc[u * 4 + 3] = fmaf(p, vv.w, acc[u * 4 + 3]);
                }
            }
        }
    }

    const float inv = 1.f / l;
    float* op = g_att + ((size_t)qi * HQ + h) * D;
#pragma unroll
    for (int u = 0; u < 8; u++) {
        float4 o = make_float4(acc[u * 4 + 0] * inv, acc[u * 4 + 1] * inv,
                               acc[u * 4 + 2] * inv, acc[u * 4 + 3] * inv);
        *(float4*)(op + u * 16 + ld * 4) = o;
    }
}

// ---------------------------------------------------------------------------
extern "C" void kernel_launch(void* const* d_in, const int* in_sizes, int n_in,
                              void* d_out, int out_size) {
    const float* hidden = (const float*)d_in[0];
    const float* cosp   = (const float*)d_in[1];
    const float* sinp   = (const float*)d_in[2];
    const float* Wq     = (const float*)d_in[3];
    const float* Wk     = (const float*)d_in[4];
    const float* Wv     = (const float*)d_in[5];
    const float* Wo     = (const float*)d_in[6];
    const float* qw     = (const float*)d_in[7];
    const float* kw     = (const float*)d_in[8];
    float* out = (float*)d_out;

    float *q, *k, *v, *att;
    cudaGetSymbolAddress((void**)&q,   g_q);
    cudaGetSymbolAddress((void**)&k,   g_k);
    cudaGetSymbolAddress((void**)&v,   g_v);
    cudaGetSymbolAddress((void**)&att, g_att);

    // QKV projections: X[4096,2048] @ W^T
    sgemm_nt<<<dim3((HQ * D) / 128, S / 128), 256>>>(hidden, Wq, q, S, HQ * D, HID);
    sgemm_nt<<<dim3((HKV * D) / 128, S / 128), 256>>>(hidden, Wk, k, S, HKV * D, HID);
    sgemm_nt<<<dim3((HKV * D) / 128, S / 128), 256>>>(hidden, Wv, v, S, HKV * D, HID);

    // Per-head RMSNorm + RoPE (in place)
    rmsnorm_rope<<<dim3(S, HQ), D>>>(q, qw, cosp, sinp, HQ);
    rmsnorm_rope<<<dim3(S, HKV), D>>>(k, kw, cosp, sinp, HKV);

    // Sliding-window attention
    attn_kernel<<<dim3(S / 64, HQ), 256>>>();

    // Output projection: att[4096,2048] @ Wo^T -> out
    sgemm_nt<<<dim3(HID / 128, S / 128), 256>>>(att, Wo, out, S, HID, HQ * D);
}

// round 3
// speedup vs baseline: 1.6576x; 1.6576x over previous
#include <cuda_runtime.h>
#include <cuda_bf16.h>
#include <math.h>
#include <cstdint>

constexpr int S = 4096, HID = 2048, HQ = 16, HKV = 8, D = 128, WINDOW = 1024;

// fp32 intermediates
__device__ float g_q[(size_t)S * HQ * D];
__device__ float g_k[(size_t)S * HKV * D];
__device__ float g_v[(size_t)S * HKV * D];
__device__ float g_att[(size_t)S * HQ * D];
// bf16 hi/lo split buffers
__device__ __nv_bfloat16 g_h_hi[(size_t)S * HID],  g_h_lo[(size_t)S * HID];
__device__ __nv_bfloat16 g_wq_hi[(size_t)HQ * D * HID], g_wq_lo[(size_t)HQ * D * HID];
__device__ __nv_bfloat16 g_wk_hi[(size_t)HKV * D * HID], g_wk_lo[(size_t)HKV * D * HID];
__device__ __nv_bfloat16 g_wv_hi[(size_t)HKV * D * HID], g_wv_lo[(size_t)HKV * D * HID];
__device__ __nv_bfloat16 g_wo_hi[(size_t)HID * HQ * D], g_wo_lo[(size_t)HID * HQ * D];
__device__ __nv_bfloat16 g_a_hi[(size_t)S * HQ * D],  g_a_lo[(size_t)S * HQ * D];

// ---------------------------------------------------------------------------
__device__ __forceinline__ uint32_t smem_u32(const void* p) {
    uint32_t a;
    asm("{ .reg .u64 t; cvta.to.shared.u64 t, %1; cvt.u32.u64 %0, t; }" : "=r"(a) : "l"(p));
    return a;
}
__device__ __forceinline__ uint32_t swz(uint32_t o) { return o ^ ((o >> 3) & 0x70); }

#define CP_ASYNC16(dst, src) \
    asm volatile("cp.async.cg.shared.global [%0], [%1], 16;" :: "r"(dst), "l"(src))
#define CP_COMMIT() asm volatile("cp.async.commit_group;" ::: "memory")
#define CP_WAIT1()  asm volatile("cp.async.wait_group 1;" ::: "memory")
#define CP_WAIT0()  asm volatile("cp.async.wait_group 0;" ::: "memory")

#define LDSM_X4(r0, r1, r2, r3, addr) \
    asm volatile("ldmatrix.sync.aligned.m8n8.x4.shared.b16 {%0,%1,%2,%3}, [%4];" \
                 : "=r"(r0), "=r"(r1), "=r"(r2), "=r"(r3) : "r"(addr))

#define MMA16816(d, a, b) \
    asm volatile("mma.sync.aligned.m16n8k16.row.col.f32.bf16.bf16.f32 " \
                 "{%0,%1,%2,%3},{%4,%5,%6,%7},{%8,%9},{%0,%1,%2,%3};" \
                 : "+f"((d)[0]), "+f"((d)[1]), "+f"((d)[2]), "+f"((d)[3]) \
                 : "r"((a)[0]), "r"((a)[1]), "r"((a)[2]), "r"((a)[3]), \
                   "r"((b)[0]), "r"((b)[1]))

// ---------------------------------------------------------------------------
// fp32 -> bf16 hi/lo split
// ---------------------------------------------------------------------------
__global__ __launch_bounds__(256)
void split_hilo(const float* __restrict__ x, __nv_bfloat16* __restrict__ hi,
                __nv_bfloat16* __restrict__ lo, int n) {
    int i = (blockIdx.x * 256 + threadIdx.x) * 4;
    if (i >= n) return;
    float4 v = *(const float4*)(x + i);
    __nv_bfloat162 h01, h23, l01, l23;
    h01.x = __float2bfloat16(v.x); h01.y = __float2bfloat16(v.y);
    h23.x = __float2bfloat16(v.z); h23.y = __float2bfloat16(v.w);
    l01.x = __float2bfloat16(v.x - __bfloat162float(h01.x));
    l01.y = __float2bfloat16(v.y - __bfloat162float(h01.y));
    l23.x = __float2bfloat16(v.z - __bfloat162float(h23.x));
    l23.y = __float2bfloat16(v.w - __bfloat162float(h23.y));
    *(__nv_bfloat162*)(hi + i)     = h01;
    *(__nv_bfloat162*)(hi + i + 2) = h23;
    *(__nv_bfloat162*)(lo + i)     = l01;
    *(__nv_bfloat162*)(lo + i + 2) = l23;
}

// ---------------------------------------------------------------------------
// Tensor-core GEMM: C[M,N] = (Ah+Al)[M,K] @ (Bh+Bl)[N,K]^T, fp32 accum.
// 128x128 CTA tile, BK=64, 8 warps (2x4), mma.sync m16n8k16 bf16.
// cp.async double-buffered SW128-swizzled smem, 128KB dynamic.
// ---------------------------------------------------------------------------
constexpr int TILE_BYTES = 128 * 64 * 2;   // 16KB per tensor tile
constexpr int BUF_BYTES  = 4 * TILE_BYTES; // Ah, Al, Bh, Bl
constexpr int GEMM_SMEM  = 2 * BUF_BYTES;  // 128KB

__global__ __launch_bounds__(256, 1)
void gemm_mma(const __nv_bfloat16* __restrict__ Ah, const __nv_bfloat16* __restrict__ Al,
              const __nv_bfloat16* __restrict__ Bh, const __nv_bfloat16* __restrict__ Bl,
              float* __restrict__ C, int N, int K) {
    extern __shared__ char smem[];
    const uint32_t sb = smem_u32(smem);
    const int tid = threadIdx.x;
    const int wid = tid >> 5;
    const int lane = tid & 31;
    const int wm = wid >> 2;          // 0..1  (64-row band)
    const int wn = wid & 3;           // 0..3  (32-col band)
    const int bm = blockIdx.y * 128;
    const int bn = blockIdx.x * 128;

    const __nv_bfloat16* srcs[4] = { Ah, Al, Bh, Bl };
    const int row0s[4] = { bm, bm, bn, bn };

    // copy chunk c (k0 = c*64) into buffer (c&1): 4 tiles x (128 rows x 8 16B-chunks)
    auto issue_copy = [&](int c) {
        const uint32_t base = sb + (uint32_t)(c & 1) * BUF_BYTES;
        const int k0 = c << 6;
#pragma unroll
        for (int t = 0; t < 4; t++) {
            const __nv_bfloat16* src = srcs[t];
            const int row0 = row0s[t];
            const uint32_t tbase = base + t * TILE_BYTES;
#pragma unroll
            for (int i = 0; i < 4; i++) {
                int idx = tid + i * 256;          // 0..1023
                int r  = idx >> 3;
                int cc = idx & 7;
                uint32_t dst = tbase + swz((uint32_t)(r * 128 + cc * 16));
                const void* s = src + (size_t)(row0 + r) * K + k0 + cc * 8;
                CP_ASYNC16(dst, s);
            }
        }
        CP_COMMIT();
    };

    float acc[4][4][4];
#pragma unroll
    for (int a = 0; a < 4; a++)
#pragma unroll
        for (int b = 0; b < 4; b++)
#pragma unroll
            for (int x = 0; x < 4; x++) acc[a][b][x] = 0.f;

    // per-lane ldmatrix addressing (SW128: chunk ^= row&7)
    const int arow = (lane & 15);                 // A sub-row within m16
    const int ahi  = lane >> 4;                   // +chunk for k8 half
    uint32_t a_rowoff[4];
#pragma unroll
    for (int mf = 0; mf < 4; mf++)
        a_rowoff[mf] = (uint32_t)((wm * 64 + mf * 16 + arow) * 128);
    const uint32_t arx = (uint32_t)(arow & 7);

    const int bnrow = (lane & 7) + ((lane >> 4) & 1) * 8;  // B sub-row (n) within n16
    const int bhi   = (lane >> 3) & 1;                     // +chunk for k8 half
    uint32_t b_rowoff[2];
#pragma unroll
    for (int bf = 0; bf < 2; bf++)
        b_rowoff[bf] = (uint32_t)((wn * 32 + bf * 16 + bnrow) * 128);
    const uint32_t brx = (uint32_t)(bnrow & 7);

    const int NC = K >> 6;
    issue_copy(0);
    if (NC > 1) issue_copy(1);

    for (int c = 0; c < NC; c++) {
        if (c < NC - 1) { CP_WAIT1(); } else { CP_WAIT0(); }
        __syncthreads();

        const uint32_t base = sb + (uint32_t)(c & 1) * BUF_BYTES;
        const uint32_t A_hi_b = base,                 A_lo_b = base + TILE_BYTES;
        const uint32_t B_hi_b = base + 2 * TILE_BYTES, B_lo_b = base + 3 * TILE_BYTES;

#pragma unroll
        for (int ks = 0; ks < 4; ks++) {
            uint32_t ah[4][4], al[4][4], bh[2][4], bl[2][4];
            const uint32_t ac = (uint32_t)(ks * 2 + ahi);
            const uint32_t bc = (uint32_t)(ks * 2 + bhi);
#pragma unroll
            for (int mf = 0; mf < 4; mf++) {
                uint32_t off = a_rowoff[mf] + ((ac ^ arx) << 4);
                LDSM_X4(ah[mf][0], ah[mf][1], ah[mf][2], ah[mf][3], A_hi_b + off);
                LDSM_X4(al[mf][0], al[mf][1], al[mf][2], al[mf][3], A_lo_b + off);
            }
#pragma unroll
            for (int bf = 0; bf < 2; bf++) {
                uint32_t off = b_rowoff[bf] + ((bc ^ brx) << 4);
                LDSM_X4(bh[bf][0], bh[bf][1], bh[bf][2], bh[bf][3], B_hi_b + off);
                LDSM_X4(bl[bf][0], bl[bf][1], bl[bf][2], bl[bf][3], B_lo_b + off);
            }
#pragma unroll
            for (int mf = 0; mf < 4; mf++)
#pragma unroll
                for (int nf = 0; nf < 4; nf++) {
                    uint32_t* bhp = &bh[nf >> 1][(nf & 1) * 2];
                    uint32_t* blp = &bl[nf >> 1][(nf & 1) * 2];
                    MMA16816(acc[mf][nf], ah[mf], bhp);
                    MMA16816(acc[mf][nf], ah[mf], blp);
                    MMA16816(acc[mf][nf], al[mf], bhp);
                }
        }
        __syncthreads();
        if (c + 2 < NC) issue_copy(c + 2);
    }

    // epilogue: frag (r = lane>>2 [+8], c = (lane&3)*2)
    const int er = lane >> 2;
    const int ec = (lane & 3) * 2;
#pragma unroll
    for (int mf = 0; mf < 4; mf++) {
        const int r0 = bm + wm * 64 + mf * 16 + er;
#pragma unroll
        for (int nf = 0; nf < 4; nf++) {
            const int cc = bn + wn * 32 + nf * 8 + ec;
            *(float2*)(C + (size_t)r0 * N + cc)       = make_float2(acc[mf][nf][0], acc[mf][nf][1]);
            *(float2*)(C + (size_t)(r0 + 8) * N + cc) = make_float2(acc[mf][nf][2], acc[mf][nf][3]);
        }
    }
}

// ---------------------------------------------------------------------------
// Fused RMSNorm + RoPE (in place on [S, H, D])
// ---------------------------------------------------------------------------
__global__ __launch_bounds__(128)
void rmsnorm_rope(float* __restrict__ X, const float* __restrict__ w,
                  const float* __restrict__ cosp, const float* __restrict__ sinp,
                  int H) {
    const int s = blockIdx.x, h = blockIdx.y, d = threadIdx.x;
    float* row = X + ((size_t)s * H + h) * D;
    float x = row[d];
    float sq = x * x;
#pragma unroll
    for (int o = 16; o > 0; o >>= 1) sq += __shfl_xor_sync(0xffffffffu, sq, o);
    __shared__ float red[4];
    __shared__ float xs[D];
    if ((d & 31) == 0) red[d >> 5] = sq;
    __syncthreads();
    float var = (red[0] + red[1] + red[2] + red[3]) * (1.0f / D);
    float xn = x * rsqrtf(var + 1e-6f) * w[d];
    xs[d] = xn;
    __syncthreads();
    float other = (d < 64) ? -xs[d + 64] : xs[d - 64];
    row[d] = fmaf(xn, cosp[s * D + d], other * sinp[s * D + d]);
}

// ---------------------------------------------------------------------------
// Sliding-window flash attention (fp32), 64 queries x 4 lanes/query per block
// ---------------------------------------------------------------------------
__global__ __launch_bounds__(256, 2)
void attn_kernel() {
    const int h   = blockIdx.y;
    const int kh  = h >> 1;
    const int qt  = blockIdx.x;
    const int tid = threadIdx.x;
    const int qi  = qt * 64 + (tid >> 2);
    const int ld  = tid & 3;

    __shared__ float Ks[32][128];
    __shared__ float Vs[32][128];

    float qr[32];
    const float* qp = g_q + ((size_t)qi * HQ + h) * D;
#pragma unroll
    for (int u = 0; u < 8; u++)
        *(float4*)&qr[u * 4] = *(const float4*)(qp + u * 16 + ld * 4);

    float m = -1e30f, l = 0.f;
    float acc[32];
#pragma unroll
    for (int d = 0; d < 32; d++) acc[d] = 0.f;

    int jlo = qt * 64 - (WINDOW - 1);
    if (jlo < 0) jlo = 0;
    int j0 = jlo & ~31;
    const int jend = qt * 64 + 64;

    for (; j0 < jend; j0 += 32) {
        __syncthreads();
#pragma unroll
        for (int u = 0; u < 4; u++) {
            int idx = tid + u * 256;
            int r = idx >> 5;
            int c = (idx & 31) * 4;
            size_t goff = ((size_t)(j0 + r) * HKV + kh) * D + c;
            *(float4*)&Ks[r][c] = *(const float4*)(g_k + goff);
            *(float4*)&Vs[r][c] = *(const float4*)(g_v + goff);
        }
        __syncthreads();

        for (int j = 0; j < 32; j++) {
            const int jj = j0 + j;
            float sv = 0.f;
#pragma unroll
            for (int u = 0; u < 8; u++) {
                float4 kv = *(const float4*)&Ks[j][u * 16 + ld * 4];
                sv = fmaf(qr[u * 4 + 0], kv.x, sv);
                sv = fmaf(qr[u * 4 + 1], kv.y, sv);
                sv = fmaf(qr[u * 4 + 2], kv.z, sv);
                sv = fmaf(qr[u * 4 + 3], kv.w, sv);
            }
            sv += __shfl_xor_sync(0xffffffffu, sv, 1);
            sv += __shfl_xor_sync(0xffffffffu, sv, 2);
            if (jj <= qi && jj > qi - WINDOW) {
                sv *= 0.088388347648318447f;
                if (sv > m) {
                    const float c = __expf(m - sv);
                    l *= c;
#pragma unroll
                    for (int d = 0; d < 32; d++) acc[d] *= c;
                    m = sv;
                }
                const float p = __expf(sv - m);
                l += p;
#pragma unroll
                for (int u = 0; u < 8; u++) {
                    float4 vv = *(const float4*)&Vs[j][u * 16 + ld * 4];
                    acc[u * 4 + 0] = fmaf(p, vv.x, acc[u * 4 + 0]);
                    acc[u * 4 + 1] = fmaf(p, vv.y, acc[u * 4 + 1]);
                    acc[u * 4 + 2] = fmaf(p, vv.z, acc[u * 4 + 2]);
                    acc[u * 4 + 3] = fmaf(p, vv.w, acc[u * 4 + 3]);
                }
            }
        }
    }

    const float inv = 1.f / l;
    float* op = g_att + ((size_t)qi * HQ + h) * D;
#pragma unroll
    for (int u = 0; u < 8; u++) {
        float4 o = make_float4(acc[u * 4 + 0] * inv, acc[u * 4 + 1] * inv,
                               acc[u * 4 + 2] * inv, acc[u * 4 + 3] * inv);
        *(float4*)(op + u * 16 + ld * 4) = o;
    }
}

// ---------------------------------------------------------------------------
extern "C" void kernel_launch(void* const* d_in, const int* in_sizes, int n_in,
                              void* d_out, int out_size) {
    const float* hidden = (const float*)d_in[0];
    const float* cosp   = (const float*)d_in[1];
    const float* sinp   = (const float*)d_in[2];
    const float* Wq     = (const float*)d_in[3];
    const float* Wk     = (const float*)d_in[4];
    const float* Wv     = (const float*)d_in[5];
    const float* Wo     = (const float*)d_in[6];
    const float* qw     = (const float*)d_in[7];
    const float* kw     = (const float*)d_in[8];
    float* out = (float*)d_out;

    float *q, *k, *v, *att;
    cudaGetSymbolAddress((void**)&q,   g_q);
    cudaGetSymbolAddress((void**)&k,   g_k);
    cudaGetSymbolAddress((void**)&v,   g_v);
    cudaGetSymbolAddress((void**)&att, g_att);
    __nv_bfloat16 *hh, *hl, *qh, *ql, *kh, *kl, *vh, *vl, *oh, *ol, *ah, *al;
    cudaGetSymbolAddress((void**)&hh, g_h_hi);  cudaGetSymbolAddress((void**)&hl, g_h_lo);
    cudaGetSymbolAddress((void**)&qh, g_wq_hi); cudaGetSymbolAddress((void**)&ql, g_wq_lo);
    cudaGetSymbolAddress((void**)&kh, g_wk_hi); cudaGetSymbolAddress((void**)&kl, g_wk_lo);
    cudaGetSymbolAddress((void**)&vh, g_wv_hi); cudaGetSymbolAddress((void**)&vl, g_wv_lo);
    cudaGetSymbolAddress((void**)&oh, g_wo_hi); cudaGetSymbolAddress((void**)&ol, g_wo_lo);
    cudaGetSymbolAddress((void**)&ah, g_a_hi);  cudaGetSymbolAddress((void**)&al, g_a_lo);

    cudaFuncSetAttribute(gemm_mma, cudaFuncAttributeMaxDynamicSharedMemorySize, GEMM_SMEM);

    const int nH = S * HID, nWq = HQ * D * HID, nWk = HKV * D * HID, nWo = HID * HQ * D;
    split_hilo<<<nH  / 1024, 256>>>(hidden, hh, hl, nH);
    split_hilo<<<nWq / 1024, 256>>>(Wq, qh, ql, nWq);
    split_hilo<<<nWk / 1024, 256>>>(Wk, kh, kl, nWk);
    split_hilo<<<nWk / 1024, 256>>>(Wv, vh, vl, nWk);
    split_hilo<<<nWo / 1024, 256>>>(Wo, oh, ol, nWo);

    gemm_mma<<<dim3((HQ * D) / 128, S / 128), 256, GEMM_SMEM>>>(hh, hl, qh, ql, q, HQ * D, HID);
    gemm_mma<<<dim3((HKV * D) / 128, S / 128), 256, GEMM_SMEM>>>(hh, hl, kh, kl, k, HKV * D, HID);
    gemm_mma<<<dim3((HKV * D) / 128, S / 128), 256, GEMM_SMEM>>>(hh, hl, vh, vl, v, HKV * D, HID);

    rmsnorm_rope<<<dim3(S, HQ), D>>>(q, qw, cosp, sinp, HQ);
    rmsnorm_rope<<<dim3(S, HKV), D>>>(k, kw, cosp, sinp, HKV);

    attn_kernel<<<dim3(S / 64, HQ), 256>>>();

    const int nA = S * HQ * D;
    split_hilo<<<nA / 1024, 256>>>(att, ah, al, nA);
    gemm_mma<<<dim3(HID / 128, S / 128), 256, GEMM_SMEM>>>(ah, al, oh, ol, out, HID, HQ * D);
}